// round 1
// baseline (speedup 1.0000x reference)
#include <cuda_runtime.h>
#include <math.h>
#include <stdint.h>

#define TT 262144
#define S 128
#define F 16
#define CHUNKS 296
#define CLEN (((TT - 1) + CHUNKS - 1) / CHUNKS)   // 886

// ---------------- scratch (device globals; no allocation allowed) ----------------
__device__ float g_logB[(size_t)TT * S];       // 134 MB
__device__ float g_E[S * S];                   // row-stochastic softmax(trans)
__device__ float g_lstart[S];
__device__ float g_iv[S * F];
__device__ float g_m2[S * F];                  // 2*mu*inv_v
__device__ float g_cst[S];                     // log_norm - 0.5*sum(mu^2*iv)
__device__ float g_P[(size_t)CHUNKS * S * S];  // 19.4 MB chunk maps (row-normalized)
__device__ float g_off[CHUNKS * S];            // per-row log offsets
__device__ float g_bound[(CHUNKS + 1) * S];    // chunk-boundary alphas

// ---------------- kernel 1: small preprocessing ----------------
__global__ void prep_kernel(const float* __restrict__ start_prob,
                            const float* __restrict__ trans,
                            const float* __restrict__ means,
                            const float* __restrict__ vars) {
    int s = threadIdx.x;  // 128 threads
    __shared__ float red[S];

    // log_softmax(start_prob)
    float sp = start_prob[s];
    red[s] = sp; __syncthreads();
    for (int o = 64; o > 0; o >>= 1) { if (s < o) red[s] = fmaxf(red[s], red[s + o]); __syncthreads(); }
    float mx = red[0]; __syncthreads();
    red[s] = expf(sp - mx); __syncthreads();
    for (int o = 64; o > 0; o >>= 1) { if (s < o) red[s] += red[s + o]; __syncthreads(); }
    float lse = mx + logf(red[0]);
    g_lstart[s] = sp - lse;

    // E[s][:] = softmax(trans[s][:])
    float m = -INFINITY;
    for (int j = 0; j < S; j++) m = fmaxf(m, trans[s * S + j]);
    float z = 0.f;
    for (int j = 0; j < S; j++) z += expf(trans[s * S + j] - m);
    float inv = 1.0f / z;
    for (int j = 0; j < S; j++) g_E[s * S + j] = expf(trans[s * S + j] - m) * inv;

    // emission constants
    float ln = 0.f, c2 = 0.f;
    for (int f = 0; f < F; f++) {
        float v = vars[s * F + f];
        v = fmaxf(v, 1e-6f);
        float iv = 1.0f / v;
        float mu = means[s * F + f];
        g_iv[s * F + f] = iv;
        g_m2[s * F + f] = 2.0f * mu * iv;
        ln += logf(6.2831853071795864f * v);
        c2 += mu * mu * iv;
    }
    g_cst[s] = -0.5f * (ln + c2);
}

// ---------------- kernel 2: log emissions (T x S) ----------------
__global__ void logb_kernel(const float* __restrict__ x) {
    int s = threadIdx.x;           // 128 threads, one per state
    int t0 = blockIdx.x * 64;      // 64 timesteps per block
    __shared__ float sx[64 * F];
    for (int i = s; i < 64 * F; i += S) sx[i] = x[(size_t)t0 * F + i];
    float iv[F], m2[F];
#pragma unroll
    for (int f = 0; f < F; f++) { iv[f] = g_iv[s * F + f]; m2[f] = g_m2[s * F + f]; }
    float cst = g_cst[s];
    __syncthreads();
    for (int t = 0; t < 64; t++) {
        float q = 0.f;
#pragma unroll
        for (int f = 0; f < F; f++) {
            float xv = sx[t * F + f];
            q = fmaf(xv, fmaf(xv, iv[f], -m2[f]), q);  // x*(x*iv - 2*mu*iv)
        }
        g_logB[(size_t)(t0 + t) * S + s] = cst - 0.5f * q;
    }
}

// ---------------- kernel 3: per-chunk transition-matrix scan (the heavy one) ----------------
// smem layout (floats): sP[16384] | sE[16384] | sbex[128] | srinv[128] | soff[128] | sred[128*17] | saux[32]
#define P1_FLOATS (16384 + 16384 + 128 + 128 + 128 + 128 * 17 + 32)
#define P1_SMEM (P1_FLOATS * 4)

__global__ void __launch_bounds__(256) phase1_kernel() {
    extern __shared__ float sm[];
    float* sP    = sm;
    float* sE    = sm + 16384;
    float* sbex  = sE + 16384;
    float* srinv = sbex + S;
    float* soff  = srinv + S;
    float* sred  = soff + S;        // padded stride 17
    float* saux  = sred + 128 * 17;

    int tid = threadIdx.x;
    int c = blockIdx.x;
    for (int i = tid; i < S * S; i += 256) sE[i] = g_E[i];
    for (int i = tid; i < S * S; i += 256) sP[i] = ((i >> 7) == (i & 127)) ? 1.0f : 0.0f;
    if (tid < S) soff[tid] = 0.0f;
    __syncthreads();

    long begin = 1 + (long)c * CLEN;
    long end = begin + CLEN;
    if (end > TT) end = TT;

    int ty = tid >> 4, tx = tid & 15;
    int r0 = ty * 8, c0 = tx * 8;

    for (long t = begin; t < end; t++) {
        // per-step emission scaling vector: bexp = exp(logB_t - max)
        float lb = 0.f;
        if (tid < S) {
            lb = g_logB[t * S + tid];
            float v = lb;
            for (int o = 16; o > 0; o >>= 1) v = fmaxf(v, __shfl_xor_sync(0xffffffffu, v, o));
            if ((tid & 31) == 0) saux[tid >> 5] = v;
        }
        __syncthreads();
        float mB = fmaxf(fmaxf(saux[0], saux[1]), fmaxf(saux[2], saux[3]));
        if (tid < S) sbex[tid] = expf(lb - mB);
        __syncthreads();

        // acc = P * E (128x128x128, 8x8 register tile per thread)
        float acc[8][8];
#pragma unroll
        for (int i = 0; i < 8; i++)
#pragma unroll
            for (int j = 0; j < 8; j++) acc[i][j] = 0.f;

#pragma unroll 2
        for (int k = 0; k < S; k++) {
            float4 e0 = *(const float4*)&sE[k * S + c0];
            float4 e1 = *(const float4*)&sE[k * S + c0 + 4];
#pragma unroll
            for (int i = 0; i < 8; i++) {
                float p = sP[(r0 + i) * S + k];
                acc[i][0] = fmaf(p, e0.x, acc[i][0]);
                acc[i][1] = fmaf(p, e0.y, acc[i][1]);
                acc[i][2] = fmaf(p, e0.z, acc[i][2]);
                acc[i][3] = fmaf(p, e0.w, acc[i][3]);
                acc[i][4] = fmaf(p, e1.x, acc[i][4]);
                acc[i][5] = fmaf(p, e1.y, acc[i][5]);
                acc[i][6] = fmaf(p, e1.z, acc[i][6]);
                acc[i][7] = fmaf(p, e1.w, acc[i][7]);
            }
        }

        // scale by bexp, local row maxima
#pragma unroll
        for (int i = 0; i < 8; i++) {
            float mrow = 0.f;
#pragma unroll
            for (int j = 0; j < 8; j++) {
                acc[i][j] *= sbex[c0 + j];
                mrow = fmaxf(mrow, acc[i][j]);
            }
            sred[(r0 + i) * 17 + tx] = mrow;
        }
        __syncthreads();
        if (tid < S) {
            float rm = 0.f;
#pragma unroll
            for (int j = 0; j < 16; j++) rm = fmaxf(rm, sred[tid * 17 + j]);
            soff[tid] += mB + logf(rm);
            srinv[tid] = 1.0f / rm;
        }
        __syncthreads();
#pragma unroll
        for (int i = 0; i < 8; i++) {
            float ri = srinv[r0 + i];
#pragma unroll
            for (int j = 0; j < 8; j++)
                sP[(r0 + i) * S + c0 + j] = acc[i][j] * ri;
        }
        __syncthreads();
    }

    for (int i = tid; i < S * S; i += 256) g_P[(size_t)c * S * S + i] = sP[i];
    if (tid < S) g_off[c * S + tid] = soff[tid];
}

// ---------------- kernel 4: sequential combine across chunk boundaries ----------------
__global__ void __launch_bounds__(512) phase2_kernel() {
    __shared__ float sb[S], sw[S], spart[4][S], smax[4];
    int tid = threadIdx.x;
    int j = tid & 127, g = tid >> 7;

    if (tid < S) {
        float b0 = g_lstart[tid] + g_logB[tid];  // alpha_0
        sb[tid] = b0;
        g_bound[tid] = b0;
    }
    __syncthreads();

    for (int c = 0; c < CHUNKS; c++) {
        if (tid < S) sw[tid] = sb[tid] + g_off[c * S + tid];
        __syncthreads();
        if (tid < S) {
            float u = sw[tid];
            for (int o = 16; o > 0; o >>= 1) u = fmaxf(u, __shfl_xor_sync(0xffffffffu, u, o));
            if ((tid & 31) == 0) smax[tid >> 5] = u;
        }
        __syncthreads();
        float m = fmaxf(fmaxf(smax[0], smax[1]), fmaxf(smax[2], smax[3]));
        if (tid < S) sw[tid] = expf(sw[tid] - m);
        __syncthreads();

        const float* base = &g_P[(size_t)c * S * S];
        float p = 0.f;
        int i0 = g * 32;
#pragma unroll 8
        for (int i = i0; i < i0 + 32; i++)
            p = fmaf(sw[i], base[i * S + j], p);
        spart[g][j] = p;
        __syncthreads();
        if (tid < S) {
            float ssum = spart[0][j] + spart[1][j] + spart[2][j] + spart[3][j];
            float nb = m + logf(ssum);
            sb[j] = nb;
            g_bound[(c + 1) * S + j] = nb;
        }
        __syncthreads();
    }
}

// ---------------- kernel 5: replay each chunk from exact boundary, write log_alpha ----------------
#define P3_FLOATS (16384 + 128 + 8)
#define P3_SMEM (P3_FLOATS * 4)

__global__ void __launch_bounds__(128) phase3_kernel(float* __restrict__ out) {
    extern __shared__ float sm[];
    float* sE = sm;
    float* sw = sm + 16384;
    float* smax = sw + S;

    int j = threadIdx.x;
    int c = blockIdx.x;
    for (int i = j; i < S * S; i += S) sE[i] = g_E[i];
    float a = g_bound[c * S + j];
    long begin = 1 + (long)c * CLEN;
    long end = begin + CLEN;
    if (end > TT) end = TT;
    if (c == 0) out[j] = a;  // t = 0 row
    __syncthreads();

    for (long t = begin; t < end; t++) {
        float u = a;
        for (int o = 16; o > 0; o >>= 1) u = fmaxf(u, __shfl_xor_sync(0xffffffffu, u, o));
        if ((j & 31) == 0) smax[j >> 5] = u;
        __syncthreads();
        float m = fmaxf(fmaxf(smax[0], smax[1]), fmaxf(smax[2], smax[3]));
        sw[j] = expf(a - m);
        __syncthreads();
        float s_ = 0.f;
#pragma unroll 8
        for (int i = 0; i < S; i++) s_ = fmaf(sw[i], sE[i * S + j], s_);
        a = m + logf(s_) + g_logB[t * S + j];
        out[t * S + j] = a;
        __syncthreads();
    }
}

// ---------------- kernel 6: final log-likelihood ----------------
__global__ void ll_kernel(float* __restrict__ out, int out_size) {
    int lane = threadIdx.x;  // 32 threads
    const float* last = out + (size_t)(TT - 1) * S;
    float v0 = last[lane], v1 = last[lane + 32], v2 = last[lane + 64], v3 = last[lane + 96];
    float m = fmaxf(fmaxf(v0, v1), fmaxf(v2, v3));
    for (int o = 16; o > 0; o >>= 1) m = fmaxf(m, __shfl_xor_sync(0xffffffffu, m, o));
    float s = expf(v0 - m) + expf(v1 - m) + expf(v2 - m) + expf(v3 - m);
    for (int o = 16; o > 0; o >>= 1) s += __shfl_xor_sync(0xffffffffu, s, o);
    if (lane == 0 && out_size > TT * S) out[(size_t)TT * S] = m + logf(s);
}

// ---------------- launch ----------------
extern "C" void kernel_launch(void* const* d_in, const int* in_sizes, int n_in,
                              void* d_out, int out_size) {
    const float* x          = (const float*)d_in[0];
    const float* start_prob = (const float*)d_in[1];
    const float* trans      = (const float*)d_in[2];
    const float* means      = (const float*)d_in[3];
    const float* vars       = (const float*)d_in[4];
    float* out = (float*)d_out;

    cudaFuncSetAttribute(phase1_kernel, cudaFuncAttributeMaxDynamicSharedMemorySize, P1_SMEM);
    cudaFuncSetAttribute(phase3_kernel, cudaFuncAttributeMaxDynamicSharedMemorySize, P3_SMEM);

    prep_kernel<<<1, 128>>>(start_prob, trans, means, vars);
    logb_kernel<<<TT / 64, 128>>>(x);
    phase1_kernel<<<CHUNKS, 256, P1_SMEM>>>();
    phase2_kernel<<<1, 512>>>();
    phase3_kernel<<<CHUNKS, 128, P3_SMEM>>>(out);
    ll_kernel<<<1, 32>>>(out, out_size);
}

// round 3
// speedup vs baseline: 12.8817x; 12.8817x over previous
#include <cuda_runtime.h>
#include <math.h>
#include <stdint.h>

#define TT 262144
#define S 128
#define F 16
#define CH 148
#define L 1772          // 148 * 1772 = 262256 >= TT
#define W 886           // warmup steps (forgetting window)

// ---------------- scratch (device globals; no allocation allowed) ----------------
__device__ float g_logB[(size_t)TT * S];       // 134 MB
__device__ float g_E[S * S];                   // row-stochastic softmax(trans)
__device__ float g_lstart[S];
__device__ float g_iv[S * F];
__device__ float g_m2[S * F];                  // 2*mu*inv_v
__device__ float g_cst[S];
__device__ float g_junc[CH * S];               // chunk c-1's vector at t = c*L (local frame)
__device__ float g_delta[CH];                  // per-chunk log-scale correction

// ---------------- kernel 1: small preprocessing ----------------
__global__ void prep_kernel(const float* __restrict__ start_prob,
                            const float* __restrict__ trans,
                            const float* __restrict__ means,
                            const float* __restrict__ vars) {
    int s = threadIdx.x;  // 128 threads
    __shared__ float red[S];

    // log_softmax(start_prob)
    float sp = start_prob[s];
    red[s] = sp; __syncthreads();
    for (int o = 64; o > 0; o >>= 1) { if (s < o) red[s] = fmaxf(red[s], red[s + o]); __syncthreads(); }
    float mx = red[0]; __syncthreads();
    red[s] = expf(sp - mx); __syncthreads();
    for (int o = 64; o > 0; o >>= 1) { if (s < o) red[s] += red[s + o]; __syncthreads(); }
    float lse = mx + logf(red[0]);
    g_lstart[s] = sp - lse;

    // E[s][:] = softmax(trans[s][:])
    float m = -INFINITY;
    for (int j = 0; j < S; j++) m = fmaxf(m, trans[s * S + j]);
    float z = 0.f;
    for (int j = 0; j < S; j++) z += expf(trans[s * S + j] - m);
    float inv = 1.0f / z;
    for (int j = 0; j < S; j++) g_E[s * S + j] = expf(trans[s * S + j] - m) * inv;

    // emission constants
    float ln = 0.f, c2 = 0.f;
    for (int f = 0; f < F; f++) {
        float v = vars[s * F + f];
        v = fmaxf(v, 1e-6f);
        float iv = 1.0f / v;
        float mu = means[s * F + f];
        g_iv[s * F + f] = iv;
        g_m2[s * F + f] = 2.0f * mu * iv;
        ln += logf(6.2831853071795864f * v);
        c2 += mu * mu * iv;
    }
    g_cst[s] = -0.5f * (ln + c2);
}

// ---------------- kernel 2: log emissions (T x S) ----------------
__global__ void logb_kernel(const float* __restrict__ x) {
    int s = threadIdx.x;           // 128 threads, one per state
    int t0 = blockIdx.x * 64;
    __shared__ float sx[64 * F];
    for (int i = s; i < 64 * F; i += S) sx[i] = x[(size_t)t0 * F + i];
    float iv[F], m2[F];
#pragma unroll
    for (int f = 0; f < F; f++) { iv[f] = g_iv[s * F + f]; m2[f] = g_m2[s * F + f]; }
    float cst = g_cst[s];
    __syncthreads();
    for (int t = 0; t < 64; t++) {
        float q = 0.f;
#pragma unroll
        for (int f = 0; f < F; f++) {
            float xv = sx[t * F + f];
            q = fmaf(xv, fmaf(xv, iv[f], -m2[f]), q);
        }
        g_logB[(size_t)(t0 + t) * S + s] = cst - 0.5f * q;
    }
}

// ---------------- kernel 3: warm-started per-chunk vector recursion ----------------
// E kept in registers: thread (j, h) owns E[h*64 + i][j], i = 0..63.
// smem: sw[128] | spart[256] | smax[32]
#define SC_FLOATS (128 + 256 + 32)
#define SC_SMEM (SC_FLOATS * 4)

__global__ void __launch_bounds__(256) scan_kernel(float* __restrict__ out) {
    extern __shared__ float sm[];
    float* sw    = sm;
    float* spart = sw + S;
    float* smax  = spart + 256;

    int tid = threadIdx.x;
    int j = tid & 127, h = tid >> 7;
    int c = blockIdx.x;

    // register-resident E column slice
    float e[64];
#pragma unroll
    for (int i = 0; i < 64; i++) e[i] = g_E[(h * 64 + i) * S + j];

    long wstart = (long)c * L;                    // first written t
    long wend = wstart + L; if (wend > TT) wend = TT;
    long t0 = (c == 0) ? 0 : (wstart - W);        // recursion anchor
    // chunks 0..CH-2 compute one junction step at t = wstart + L
    long tstop = (c < CH - 1) ? (wstart + L + 1) : wend;

    float a = 0.f, lb = 0.f;
    if (tid < S) {
        if (c == 0) { a = g_lstart[j] + g_logB[j]; out[j] = a; }
        else        a = g_logB[(size_t)t0 * S + j];   // any positive start; direction forgets it
        lb = g_logB[(size_t)(t0 + 1) * S + j];
    }
    __syncthreads();

    for (long t = t0 + 1; t < tstop; t++) {
        if (tid < S) {
            float u = a;
#pragma unroll
            for (int o = 16; o > 0; o >>= 1) u = fmaxf(u, __shfl_xor_sync(0xffffffffu, u, o));
            if ((tid & 31) == 0) smax[tid >> 5] = u;
        }
        __syncthreads();
        float m = fmaxf(fmaxf(smax[0], smax[1]), fmaxf(smax[2], smax[3]));
        if (tid < S) sw[j] = __expf(a - m);
        __syncthreads();

        // prefetch next logB row while matvec runs
        float lbn = 0.f;
        if (tid < S && t + 1 < tstop) lbn = g_logB[(size_t)(t + 1) * S + j];

        // matvec: p_j = sum_i sw[i] * E[i][j]; sw reads are warp-broadcast
        const float* wb = sw + h * 64;
        float p0 = 0.f, p1 = 0.f, p2 = 0.f, p3 = 0.f;
#pragma unroll
        for (int i = 0; i < 64; i += 4) {
            p0 = fmaf(wb[i],     e[i],     p0);
            p1 = fmaf(wb[i + 1], e[i + 1], p1);
            p2 = fmaf(wb[i + 2], e[i + 2], p2);
            p3 = fmaf(wb[i + 3], e[i + 3], p3);
        }
        spart[h * S + j] = (p0 + p1) + (p2 + p3);
        __syncthreads();

        if (tid < S) {
            float s_ = spart[j] + spart[S + j];
            a = m + __logf(s_) + lb;
            if (t >= wstart && t < wend) out[(size_t)t * S + j] = a;
            else if (t == wstart + L)    g_junc[(c + 1) * S + j] = a;
            lb = lbn;
        }
        __syncthreads();
    }
}

// ---------------- kernel 4: sequential per-chunk scalar correction ----------------
__global__ void delta_kernel(const float* __restrict__ out) {
    __shared__ float red[S];
    __shared__ float smx[S];
    int j = threadIdx.x;  // 128
    float d = 0.f;
    if (j == 0) g_delta[0] = 0.f;

    for (int c = 1; c < CH; c++) {
        float ja = g_junc[c * S + j];
        float oa = out[(size_t)c * L * S + j];
        // lse(junc) - lse(out_row): exact chunk-frame offset if directions match
        smx[j] = ja; __syncthreads();
        for (int o = 64; o > 0; o >>= 1) { if (j < o) smx[j] = fmaxf(smx[j], smx[j + o]); __syncthreads(); }
        float m1 = smx[0]; __syncthreads();
        red[j] = __expf(ja - m1); __syncthreads();
        for (int o = 64; o > 0; o >>= 1) { if (j < o) red[j] += red[j + o]; __syncthreads(); }
        float lse1 = m1 + __logf(red[0]); __syncthreads();

        smx[j] = oa; __syncthreads();
        for (int o = 64; o > 0; o >>= 1) { if (j < o) smx[j] = fmaxf(smx[j], smx[j + o]); __syncthreads(); }
        float m2 = smx[0]; __syncthreads();
        red[j] = __expf(oa - m2); __syncthreads();
        for (int o = 64; o > 0; o >>= 1) { if (j < o) red[j] += red[j + o]; __syncthreads(); }
        float lse2 = m2 + __logf(red[0]); __syncthreads();

        d += lse1 - lse2;
        if (j == 0) g_delta[c] = d;
        __syncthreads();
    }
}

// ---------------- kernel 5: apply per-chunk offsets (rows t >= L) ----------------
__global__ void fix_kernel(float* __restrict__ out) {
    size_t base = (size_t)L * S;                        // first element needing fixup
    size_t n4 = ((size_t)TT * S - base) / 4;
    size_t i4 = (size_t)blockIdx.x * blockDim.x + threadIdx.x;
    if (i4 >= n4) return;
    size_t e = base + i4 * 4;
    int c = (int)((e / S) / L);
    float d = g_delta[c];
    float4* p = (float4*)(out + e);
    float4 v = *p;
    v.x += d; v.y += d; v.z += d; v.w += d;
    *p = v;
}

// ---------------- kernel 6: final log-likelihood ----------------
__global__ void ll_kernel(float* __restrict__ out, int out_size) {
    int lane = threadIdx.x;  // 32 threads
    const float* last = out + (size_t)(TT - 1) * S;
    float v0 = last[lane], v1 = last[lane + 32], v2 = last[lane + 64], v3 = last[lane + 96];
    float m = fmaxf(fmaxf(v0, v1), fmaxf(v2, v3));
    for (int o = 16; o > 0; o >>= 1) m = fmaxf(m, __shfl_xor_sync(0xffffffffu, m, o));
    float s = __expf(v0 - m) + __expf(v1 - m) + __expf(v2 - m) + __expf(v3 - m);
    for (int o = 16; o > 0; o >>= 1) s += __shfl_xor_sync(0xffffffffu, s, o);
    if (lane == 0 && out_size > TT * S) out[(size_t)TT * S] = m + __logf(s);
}

// ---------------- launch ----------------
extern "C" void kernel_launch(void* const* d_in, const int* in_sizes, int n_in,
                              void* d_out, int out_size) {
    const float* x          = (const float*)d_in[0];
    const float* start_prob = (const float*)d_in[1];
    const float* trans      = (const float*)d_in[2];
    const float* means      = (const float*)d_in[3];
    const float* vars       = (const float*)d_in[4];
    float* out = (float*)d_out;

    prep_kernel<<<1, 128>>>(start_prob, trans, means, vars);
    logb_kernel<<<TT / 64, 128>>>(x);
    scan_kernel<<<CH, 256, SC_SMEM>>>(out);
    delta_kernel<<<1, 128>>>(out);
    size_t n4 = ((size_t)TT * S - (size_t)L * S) / 4;
    fix_kernel<<<(unsigned)((n4 + 255) / 256), 256>>>(out);
    ll_kernel<<<1, 32>>>(out, out_size);
}

// round 5
// speedup vs baseline: 29.4421x; 2.2856x over previous
#include <cuda_runtime.h>
#include <math.h>
#include <stdint.h>

#define TT 262144
#define S 128
#define F 16
#define CH 296
#define L 886           // 296 * 886 = 262256 >= TT
#define W 256           // warmup steps (forgetting window)

// ---------------- scratch (device globals; no allocation allowed) ----------------
__device__ float g_logB[(size_t)TT * S];       // 134 MB
__device__ float g_E[S * S];                   // row-stochastic softmax(trans)
__device__ float g_lstart[S];
__device__ float g_iv[S * F];
__device__ float g_m2[S * F];
__device__ float g_cst[S];
__device__ float g_junc[CH * S];               // chunk c-1's vector at t = c*L (local frame)
__device__ float g_dloc[CH];                   // per-junction local offsets
__device__ float g_delta[CH];                  // prefix-summed per-chunk corrections

// ---------------- kernel 1: small preprocessing ----------------
__global__ void prep_kernel(const float* __restrict__ start_prob,
                            const float* __restrict__ trans,
                            const float* __restrict__ means,
                            const float* __restrict__ vars) {
    int s = threadIdx.x;  // 128 threads
    __shared__ float red[S];

    float sp = start_prob[s];
    red[s] = sp; __syncthreads();
    for (int o = 64; o > 0; o >>= 1) { if (s < o) red[s] = fmaxf(red[s], red[s + o]); __syncthreads(); }
    float mx = red[0]; __syncthreads();
    red[s] = expf(sp - mx); __syncthreads();
    for (int o = 64; o > 0; o >>= 1) { if (s < o) red[s] += red[s + o]; __syncthreads(); }
    float lse = mx + logf(red[0]);
    g_lstart[s] = sp - lse;

    float m = -INFINITY;
    for (int j = 0; j < S; j++) m = fmaxf(m, trans[s * S + j]);
    float z = 0.f;
    for (int j = 0; j < S; j++) z += expf(trans[s * S + j] - m);
    float inv = 1.0f / z;
    for (int j = 0; j < S; j++) g_E[s * S + j] = expf(trans[s * S + j] - m) * inv;

    float ln = 0.f, c2 = 0.f;
    for (int f = 0; f < F; f++) {
        float v = vars[s * F + f];
        v = fmaxf(v, 1e-6f);
        float iv = 1.0f / v;
        float mu = means[s * F + f];
        g_iv[s * F + f] = iv;
        g_m2[s * F + f] = 2.0f * mu * iv;
        ln += logf(6.2831853071795864f * v);
        c2 += mu * mu * iv;
    }
    g_cst[s] = -0.5f * (ln + c2);
}

// ---------------- kernel 2: log emissions (T x S) ----------------
__global__ void logb_kernel(const float* __restrict__ x) {
    int s = threadIdx.x;
    int t0 = blockIdx.x * 64;
    __shared__ float sx[64 * F];
    for (int i = s; i < 64 * F; i += S) sx[i] = x[(size_t)t0 * F + i];
    float iv[F], m2[F];
#pragma unroll
    for (int f = 0; f < F; f++) { iv[f] = g_iv[s * F + f]; m2[f] = g_m2[s * F + f]; }
    float cst = g_cst[s];
    __syncthreads();
    for (int t = 0; t < 64; t++) {
        float q = 0.f;
#pragma unroll
        for (int f = 0; f < F; f++) {
            float xv = sx[t * F + f];
            q = fmaf(xv, fmaf(xv, iv[f], -m2[f]), q);
        }
        g_logB[(size_t)(t0 + t) * S + s] = cst - 0.5f * q;
    }
}

// ---------------- kernel 3: warm-started per-chunk vector recursion ----------------
// 256 threads; thread (j, h) owns E[h*64 + i][j] in registers. 2 CTAs per SM.
#define SC_FLOATS (128 + 256 + 8)
#define SC_SMEM (SC_FLOATS * 4)

__global__ void __launch_bounds__(256, 2) scan_kernel(float* __restrict__ out) {
    extern __shared__ float sm[];
    float* sw    = sm;              // 128, float4-aligned
    float* spart = sw + S;          // 256
    float* smax  = spart + 256;     // 4 (+pad)

    int tid = threadIdx.x;
    int j = tid & 127, h = tid >> 7;
    int c = blockIdx.x;

    float e[64];
#pragma unroll
    for (int i = 0; i < 64; i++) e[i] = g_E[(h * 64 + i) * S + j];

    long wstart = (long)c * L;
    long wend = wstart + L; if (wend > TT) wend = TT;
    long t0 = (c == 0) ? 0 : (wstart - W);
    long tstop = (c < CH - 1) ? (wstart + L + 1) : wend;

    // all 256 threads carry a (h-duplicated) so max-reduce uses all warps
    float a, lb;
    if (c == 0) {
        a = g_lstart[j] + g_logB[j];
        if (h == 0) out[j] = a;
    } else {
        a = g_logB[(size_t)t0 * S + j];   // arbitrary positive start; direction forgotten in W steps
    }
    lb = g_logB[(size_t)(t0 + 1) * S + j];

    for (long t = t0 + 1; t < tstop; t++) {
        // 1) max over 128 (each warp reduces its 32; warps 4-7 duplicate 0-3)
        float u = a;
#pragma unroll
        for (int o = 16; o > 0; o >>= 1) u = fmaxf(u, __shfl_xor_sync(0xffffffffu, u, o));
        if (h == 0 && (tid & 31) == 0) smax[tid >> 5] = u;
        __syncthreads();
        float m = fmaxf(fmaxf(smax[0], smax[1]), fmaxf(smax[2], smax[3]));
        if (h == 0) sw[j] = __expf(a - m);
        __syncthreads();

        // prefetch next logB row during matvec
        float lbn = 0.f;
        if (t + 1 < tstop) lbn = g_logB[(size_t)(t + 1) * S + j];

        // 2) matvec half: p_j = sum_{i in half h} sw[i] * E[i][j]
        const float4* wb4 = (const float4*)(sw + h * 64);
        float p0 = 0.f, p1 = 0.f, p2 = 0.f, p3 = 0.f;
#pragma unroll
        for (int i = 0; i < 16; i++) {
            float4 w = wb4[i];
            p0 = fmaf(w.x, e[4 * i],     p0);
            p1 = fmaf(w.y, e[4 * i + 1], p1);
            p2 = fmaf(w.z, e[4 * i + 2], p2);
            p3 = fmaf(w.w, e[4 * i + 3], p3);
        }
        spart[h * S + j] = (p0 + p1) + (p2 + p3);
        __syncthreads();

        // 3) combine + emission
        float s_ = spart[j] + spart[S + j];
        a = m + __logf(s_) + lb;
        if (h == 0) {
            if (t >= wstart && t < wend) out[(size_t)t * S + j] = a;
            else if (t == wstart + L)    g_junc[(c + 1) * S + j] = a;
        }
        lb = lbn;
    }
}

// ---------------- kernel 4a: parallel per-junction local offsets ----------------
__global__ void delta_local_kernel(const float* __restrict__ out) {
    int c = blockIdx.x + 1;          // 1..CH-1
    int j = threadIdx.x;             // 128
    __shared__ float s4[8];

    float ja = g_junc[c * S + j];
    float oa = out[(size_t)c * L * S + j];

    // lse over ja
    float u = ja;
#pragma unroll
    for (int o = 16; o > 0; o >>= 1) u = fmaxf(u, __shfl_xor_sync(0xffffffffu, u, o));
    if ((j & 31) == 0) s4[j >> 5] = u;
    __syncthreads();
    float m1 = fmaxf(fmaxf(s4[0], s4[1]), fmaxf(s4[2], s4[3]));
    float z = __expf(ja - m1);
#pragma unroll
    for (int o = 16; o > 0; o >>= 1) z += __shfl_xor_sync(0xffffffffu, z, o);
    if ((j & 31) == 0) s4[4 + (j >> 5)] = z;
    __syncthreads();
    float lse1 = m1 + __logf(s4[4] + s4[5] + s4[6] + s4[7]);
    __syncthreads();

    // lse over oa
    u = oa;
#pragma unroll
    for (int o = 16; o > 0; o >>= 1) u = fmaxf(u, __shfl_xor_sync(0xffffffffu, u, o));
    if ((j & 31) == 0) s4[j >> 5] = u;
    __syncthreads();
    float m2 = fmaxf(fmaxf(s4[0], s4[1]), fmaxf(s4[2], s4[3]));
    z = __expf(oa - m2);
#pragma unroll
    for (int o = 16; o > 0; o >>= 1) z += __shfl_xor_sync(0xffffffffu, z, o);
    if ((j & 31) == 0) s4[4 + (j >> 5)] = z;
    __syncthreads();
    float lse2 = m2 + __logf(s4[4] + s4[5] + s4[6] + s4[7]);

    if (j == 0) g_dloc[c] = lse1 - lse2;
}

// ---------------- kernel 4b: tiny prefix scan over CH offsets ----------------
__global__ void delta_scan_kernel() {
    if (threadIdx.x == 0) {
        float d = 0.f;
        g_delta[0] = 0.f;
        for (int c = 1; c < CH; c++) { d += g_dloc[c]; g_delta[c] = d; }
    }
}

// ---------------- kernel 5: apply per-chunk offsets (rows t >= L) ----------------
__global__ void fix_kernel(float* __restrict__ out) {
    size_t base = (size_t)L * S;
    size_t n4 = ((size_t)TT * S - base) / 4;
    size_t i4 = (size_t)blockIdx.x * blockDim.x + threadIdx.x;
    if (i4 >= n4) return;
    size_t e = base + i4 * 4;
    int c = (int)((e / S) / L);
    float d = g_delta[c];
    float4* p = (float4*)(out + e);
    float4 v = *p;
    v.x += d; v.y += d; v.z += d; v.w += d;
    *p = v;
}

// ---------------- kernel 6: final log-likelihood ----------------
__global__ void ll_kernel(float* __restrict__ out, int out_size) {
    int lane = threadIdx.x;  // 32
    const float* last = out + (size_t)(TT - 1) * S;
    float v0 = last[lane], v1 = last[lane + 32], v2 = last[lane + 64], v3 = last[lane + 96];
    float m = fmaxf(fmaxf(v0, v1), fmaxf(v2, v3));
    for (int o = 16; o > 0; o >>= 1) m = fmaxf(m, __shfl_xor_sync(0xffffffffu, m, o));
    float s = __expf(v0 - m) + __expf(v1 - m) + __expf(v2 - m) + __expf(v3 - m);
    for (int o = 16; o > 0; o >>= 1) s += __shfl_xor_sync(0xffffffffu, s, o);
    if (lane == 0 && out_size > TT * S) out[(size_t)TT * S] = m + __logf(s);
}

// ---------------- launch ----------------
extern "C" void kernel_launch(void* const* d_in, const int* in_sizes, int n_in,
                              void* d_out, int out_size) {
    const float* x          = (const float*)d_in[0];
    const float* start_prob = (const float*)d_in[1];
    const float* trans      = (const float*)d_in[2];
    const float* means      = (const float*)d_in[3];
    const float* vars       = (const float*)d_in[4];
    float* out = (float*)d_out;

    prep_kernel<<<1, 128>>>(start_prob, trans, means, vars);
    logb_kernel<<<TT / 64, 128>>>(x);
    scan_kernel<<<CH, 256, SC_SMEM>>>(out);
    delta_local_kernel<<<CH - 1, 128>>>(out);
    delta_scan_kernel<<<1, 32>>>();
    size_t n4 = ((size_t)TT * S - (size_t)L * S) / 4;
    fix_kernel<<<(unsigned)((n4 + 255) / 256), 256>>>(out);
    ll_kernel<<<1, 32>>>(out, out_size);
}